// round 13
// baseline (speedup 1.0000x reference)
#include <cuda_runtime.h>
#include <math.h>

#define BATCH 8192
#define KN 8
#define TT 20
#define FF 7
#define HH 128
// encoder shape: 256 threads, 16 seqs (2 groups of 8), 2 blocks/SM
#define ENB 16
#define EHP 20         // padded [k][s] stride: 16 data + 4 pad
#define ETBLK (BATCH/ENB)   // 512 target blocks
// decoder shape (R6): 128 threads, 8 seqs
#define NB 8
#define SP 4           // seq pairs per thread (both kernels)
#define HP 12
#define PRED 25
#define NK 32

typedef unsigned long long u64;

// ---------------- f32x2 helpers ----------------------------------------------
__device__ __forceinline__ void fma2(u64 &a, u64 x, u64 y){
    asm("fma.rn.f32x2 %0, %1, %2, %0;" : "+l"(a) : "l"(x), "l"(y));
}
__device__ __forceinline__ u64 pk(float lo, float hi){
    u64 r; asm("mov.b64 %0, {%1,%2};" : "=l"(r) : "f"(lo), "f"(hi)); return r;
}
__device__ __forceinline__ float2 up2(u64 a){
    float lo, hi; asm("mov.b64 {%0,%1}, %2;" : "=f"(lo), "=f"(hi) : "l"(a));
    return make_float2(lo, hi);
}
__device__ __forceinline__ float fast_sig(float v){
    return __fdividef(1.f, 1.f + __expf(-v));
}
__device__ __forceinline__ float fast_tanh(float v){
    return 1.f - __fdividef(2.f, 1.f + __expf(2.f * v));
}

// ---------------- scratch ------------------------------------------------------
__device__ float g_ht[BATCH * HH];
__device__ float g_hn[BATCH * KN * HH];
__device__ float g_y1[BATCH * 64 * 64];
__device__ float g_pool[BATCH * 32];
__device__ float g_fused[BATCH * HH];
__device__ float g_wte[NK * 512 * 4];   // w_hh transposed [kk][row][4]
__device__ float g_wtn[NK * 512 * 4];
__device__ float g_wtd[NK * 512 * 4];

// ---------------- w_hh transpose: [row][k] -> [kk][row][4] --------------------
__global__ void transpose_kernel(const float* __restrict__ w, float* __restrict__ wt){
    int i = blockIdx.x * 256 + threadIdx.x;
    int row = i >> 7, k = i & 127;
    int kk = k >> 2, r = k & 3;
    wt[(((kk << 9) + row) << 2) + r] = w[i];
}

// ---------------- merged encoder: 256 threads, 2 seq-groups, 2 blocks/SM -------
__global__ __launch_bounds__(256, 2) void enc_kernel(
    const float* __restrict__ tgt_x, const float* __restrict__ nb_x,
    const float* __restrict__ e_wih, const float* __restrict__ n_wih,
    const float* __restrict__ e_bi,  const float* __restrict__ e_bh,
    const float* __restrict__ n_bi,  const float* __restrict__ n_bh)
{
    extern __shared__ float sm[];
    float* s_x   = sm;                       // ENB*TT*FF = 2240
    float* s_h   = s_x + ENB * TT * FF;      // 2 * 128 * EHP = 5120
    float* s_wih = s_h + 2 * HH * EHP;       // 3584
    float* s_b   = s_wih + 4 * HH * FF;      // 512

    const int tid = threadIdx.x;
    const int j = tid & 127;                 // hidden unit
    const int g = tid >> 7;                  // seq group 0..1 (seqs g*8..g*8+7)

    const bool is_tgt = (blockIdx.x < ETBLK);
    const int seq0 = (is_tgt ? blockIdx.x : (blockIdx.x - ETBLK)) * ENB;
    const float* x    = is_tgt ? tgt_x : nb_x;
    const float* wih  = is_tgt ? e_wih : n_wih;
    const float* bi   = is_tgt ? e_bi  : n_bi;
    const float* bh   = is_tgt ? e_bh  : n_bh;
    const float* wt   = is_tgt ? g_wte : g_wtn;
    float* h_out      = is_tgt ? g_ht  : g_hn;

    for (int i = tid; i < 4 * HH * FF; i += 256) s_wih[i] = wih[i];
    if (tid < 512) { s_b[tid] = bi[tid] + bh[tid]; }
    for (int i = tid + 256; i < 512; i += 256) s_b[i] = bi[i] + bh[i];
    for (int i = tid; i < ENB * TT * FF; i += 256) s_x[i] = x[(long)seq0 * (TT * FF) + i];
    for (int i = tid; i < HH * EHP; i += 256) s_h[i] = 0.f;
    __syncthreads();

    float bbv[4], wi[4][FF];
#pragma unroll
    for (int r = 0; r < 4; r++) {
        bbv[r] = s_b[r * HH + j];
#pragma unroll
        for (int f = 0; f < FF; f++) wi[r][f] = s_wih[(r * HH + j) * FF + f];
    }
    u64 c2[SP];
#pragma unroll
    for (int sp = 0; sp < SP; sp++) c2[sp] = 0ull;

    const float4* wt4 = (const float4*)wt;
    int cur = 0;
    u64 hu[SP];

    for (int t = 0; t < TT; t++) {
        const float* hc = s_h + cur * HH * EHP;
        float* hn = s_h + (cur ^ 1) * HH * EHP;

        u64 acc[4][SP];
#pragma unroll
        for (int sp = 0; sp < SP; sp++) {
            const float* xa = s_x + ((g * 8 + 2 * sp) * TT + t) * FF;
            const float* xb = xa + TT * FF;
            float A[4], B[4];
#pragma unroll
            for (int r = 0; r < 4; r++) { A[r] = bbv[r]; B[r] = bbv[r]; }
#pragma unroll
            for (int f = 0; f < FF; f++) {
                float va = xa[f], vb = xb[f];
#pragma unroll
                for (int r = 0; r < 4; r++) {
                    A[r] = fmaf(wi[r][f], va, A[r]);
                    B[r] = fmaf(wi[r][f], vb, B[r]);
                }
            }
#pragma unroll
            for (int r = 0; r < 4; r++) acc[r][sp] = pk(A[r], B[r]);
        }

        const ulonglong2* h2 = (const ulonglong2*)hc;   // EHP/4=5 u2 per k-row
#define KSTEP(CMP, KOFF) { \
            const ulonglong2* hb = h2 + ((kk << 2) + (KOFF)) * (EHP / 4) + (g << 1); \
            ulonglong2 hA = hb[0], hB = hb[1]; \
            u64 hp[SP] = {hA.x, hA.y, hB.x, hB.y}; \
            u64 W0 = pk(qa.CMP, qa.CMP), W1 = pk(qb.CMP, qb.CMP); \
            u64 W2 = pk(qc.CMP, qc.CMP), W3 = pk(qd.CMP, qd.CMP); \
            _Pragma("unroll") \
            for (int sp = 0; sp < SP; sp++) { \
                fma2(acc[0][sp], W0, hp[sp]); \
                fma2(acc[1][sp], W1, hp[sp]); \
                fma2(acc[2][sp], W2, hp[sp]); \
                fma2(acc[3][sp], W3, hp[sp]); \
            } }

        for (int kk = 0; kk < NK; kk++) {
            float4 qa = wt4[(kk << 9) + j];
            float4 qb = wt4[(kk << 9) + j + 128];
            float4 qc = wt4[(kk << 9) + j + 256];
            float4 qd = wt4[(kk << 9) + j + 384];
            KSTEP(x, 0) KSTEP(y, 1) KSTEP(z, 2) KSTEP(w, 3)
        }
#undef KSTEP

#pragma unroll
        for (int sp = 0; sp < SP; sp++) {
            float2 xi = up2(acc[0][sp]);
            float2 xf = up2(acc[1][sp]);
            float2 xg = up2(acc[2][sp]);
            float2 xo = up2(acc[3][sp]);
            float i0 = fast_sig(xi.x), i1 = fast_sig(xi.y);
            float f0 = fast_sig(xf.x), f1 = fast_sig(xf.y);
            float g0 = fast_tanh(xg.x), g1 = fast_tanh(xg.y);
            float o0 = fast_sig(xo.x), o1 = fast_sig(xo.y);
            float2 cc = up2(c2[sp]);
            float cn0 = fmaf(f0, cc.x, i0 * g0);
            float cn1 = fmaf(f1, cc.y, i1 * g1);
            c2[sp] = pk(cn0, cn1);
            hu[sp] = pk(o0 * fast_tanh(cn0), o1 * fast_tanh(cn1));
        }
        ulonglong2* hw = (ulonglong2*)(hn + j * EHP + g * 8);
        hw[0] = make_ulonglong2(hu[0], hu[1]);
        hw[1] = make_ulonglong2(hu[2], hu[3]);
        __syncthreads();
        cur ^= 1;
    }

    const float* hf = s_h + cur * HH * EHP;
    for (int i = tid; i < ENB * HH; i += 256) {
        int s = i >> 7, k = i & 127;
        h_out[(long)(seq0 + s) * HH + k] = hf[k * EHP + s];
    }
}

// ---------------- conv1: sparse social grid, weights staged in smem -----------
__global__ __launch_bounds__(256) void conv1_kernel(
    const float* __restrict__ w1, const float* __restrict__ b1)
{
    extern __shared__ float sm[];
    float* s_v = sm;                 // 8*9*132
    float* s_w = sm + 8 * 9 * 132;   // 32*9*132
    const int tid = threadIdx.x;
    const int b0 = blockIdx.x * 8;

    for (int i = tid; i < 8 * 9 * 128; i += 256) {
        int b = i / 1152, r = i % 1152, cell = r >> 7, c = r & 127;
        float v = (cell == 0) ? g_ht[(b0 + b) * HH + c]
                              : g_hn[((b0 + b) * KN + cell - 1) * HH + c];
        s_v[(b * 9 + cell) * 132 + c] = v;
    }

    const int o = tid >> 3, b = tid & 7;
    const float* vb = s_v + b * 1188;

    for (int half = 0; half < 2; half++) {
        __syncthreads();
        for (int i = tid; i < 32 * 1152; i += 256) {
            int oo = i / 1152, r = i % 1152, c = r / 9, tap = r % 9;
            s_w[oo * 1188 + tap * 132 + c] = w1[half * 32 * 1152 + i];
        }
        __syncthreads();

        const int och = half * 32 + o;
        const float bias = __ldg(b1 + och);
        const float* wb = s_w + o * 1188;
        const int CY[9] = {4, 0, 0, 0, 0, 0, 0, 0, 1};
        const int CX[9] = {4, 1, 2, 3, 4, 5, 6, 7, 0};

        for (int p = 0; p < 8; p++) {
            u64 acc[8];
#pragma unroll
            for (int q = 0; q < 8; q++) acc[q] = pk(bias, 0.f);
#pragma unroll
            for (int ci = 0; ci < 9; ci++) {
                const int cx = CX[ci];
                int dy = CY[ci] - p;
                if (dy < -1 || dy > 1) continue;
                const ulonglong2* vp  = (const ulonglong2*)(vb + ci * 132);
                const ulonglong2* wL  = (const ulonglong2*)(wb + ((dy + 1) * 3 + 2) * 132);
                const ulonglong2* wC  = (const ulonglong2*)(wb + ((dy + 1) * 3 + 1) * 132);
                const ulonglong2* wR  = (const ulonglong2*)(wb + ((dy + 1) * 3 + 0) * 132);
#pragma unroll 8
                for (int cc = 0; cc < 32; cc++) {
                    ulonglong2 vv = vp[cc];
                    if (cx - 1 >= 0) {
                        ulonglong2 wv = wL[cc];
                        fma2(acc[cx - 1], wv.x, vv.x);
                        fma2(acc[cx - 1], wv.y, vv.y);
                    }
                    {
                        ulonglong2 wv = wC[cc];
                        fma2(acc[cx], wv.x, vv.x);
                        fma2(acc[cx], wv.y, vv.y);
                    }
                    if (cx + 1 <= 7) {
                        ulonglong2 wv = wR[cc];
                        fma2(acc[cx + 1], wv.x, vv.x);
                        fma2(acc[cx + 1], wv.y, vv.y);
                    }
                }
            }
            float oq[8];
#pragma unroll
            for (int q = 0; q < 8; q++) {
                float2 f2 = up2(acc[q]);
                oq[q] = fmaxf(f2.x + f2.y, 0.f);
            }
            float4* dst = (float4*)(g_y1 + ((long)(b0 + b) * 64 + och) * 64 + p * 8);
            dst[0] = make_float4(oq[0], oq[1], oq[2], oq[3]);
            dst[1] = make_float4(oq[4], oq[5], oq[6], oq[7]);
        }
    }
}

// ---------------- conv2 + relu + maxpool ---------------------------------------
__global__ __launch_bounds__(256) void conv2_kernel(
    const float* __restrict__ w2, const float* __restrict__ b2)
{
    extern __shared__ float sm[];
    float* s_y = sm;                 // 8192
    float* s_w = sm + 8192;          // 32*577
    const int tid = threadIdx.x;
    const int b0 = blockIdx.x * 2;

    for (int i = tid; i < 8192; i += 256) s_y[i] = g_y1[(long)b0 * 4096 + i];
    for (int i = tid; i < 32 * 576; i += 256) {
        int c2 = i / 576, r = i % 576;
        s_w[c2 * 577 + r] = w2[i];
    }
    __syncthreads();

    const int b  = tid >> 7;
    const int cp = (tid >> 3) & 15;
    const int p  = tid & 7;
    const int c2a = cp, c2b = cp + 16;

    u64 acca[4], accb[4];
#pragma unroll
    for (int m = 0; m < 4; m++) { acca[m] = 0ull; accb[m] = 0ull; }

    for (int ty = 0; ty < 3; ty++) {
        int ip = p + ty - 1;
        if (ip < 0 || ip > 7) continue;
        for (int c1 = 0; c1 < 64; c1++) {
            const float4* yr = (const float4*)(s_y + ((b * 64 + c1) * 64 + ip * 8));
            float4 a0 = yr[0], a1 = yr[1];
            u64 C0 = pk(a0.x, a0.y), C1 = pk(a0.z, a0.w);
            u64 C2 = pk(a1.x, a1.y), C3 = pk(a1.z, a1.w);
            u64 L0 = pk(0.f,  a0.x), L1 = pk(a0.y, a0.z);
            u64 L2 = pk(a0.w, a1.x), L3 = pk(a1.y, a1.z);
            u64 R3 = pk(a1.w, 0.f);
            const float* wpa = s_w + c2a * 577 + c1 * 9 + ty * 3;
            const float* wpb = s_w + c2b * 577 + c1 * 9 + ty * 3;
            u64 W0a = pk(wpa[0], wpa[0]), W1a = pk(wpa[1], wpa[1]), W2a = pk(wpa[2], wpa[2]);
            u64 W0b = pk(wpb[0], wpb[0]), W1b = pk(wpb[1], wpb[1]), W2b = pk(wpb[2], wpb[2]);
            fma2(acca[0], W1a, C0); fma2(acca[1], W1a, C1);
            fma2(acca[2], W1a, C2); fma2(acca[3], W1a, C3);
            fma2(acca[0], W0a, L0); fma2(acca[1], W0a, L1);
            fma2(acca[2], W0a, L2); fma2(acca[3], W0a, L3);
            fma2(acca[0], W2a, L1); fma2(acca[1], W2a, L2);
            fma2(acca[2], W2a, L3); fma2(acca[3], W2a, R3);
            fma2(accb[0], W1b, C0); fma2(accb[1], W1b, C1);
            fma2(accb[2], W1b, C2); fma2(accb[3], W1b, C3);
            fma2(accb[0], W0b, L0); fma2(accb[1], W0b, L1);
            fma2(accb[2], W0b, L2); fma2(accb[3], W0b, L3);
            fma2(accb[0], W2b, L1); fma2(accb[1], W2b, L2);
            fma2(accb[2], W2b, L3); fma2(accb[3], W2b, R3);
        }
    }
    float bia = __ldg(b2 + c2a), bib = __ldg(b2 + c2b);
    float ma = 0.f, mb = 0.f;
#pragma unroll
    for (int m = 0; m < 4; m++) {
        float2 fa = up2(acca[m]);
        float2 fb = up2(accb[m]);
        ma = fmaxf(ma, fmaxf(fa.x, fa.y) + bia);
        mb = fmaxf(mb, fmaxf(fb.x, fb.y) + bib);
    }
    for (int off = 4; off; off >>= 1) {
        ma = fmaxf(ma, __shfl_xor_sync(0xffffffffu, ma, off));
        mb = fmaxf(mb, __shfl_xor_sync(0xffffffffu, mb, off));
    }
    if (p == 0) {
        g_pool[(b0 + b) * 32 + c2a] = ma;
        g_pool[(b0 + b) * 32 + c2b] = mb;
    }
}

// ---------------- fusion --------------------------------------------------------
__global__ __launch_bounds__(512) void fuse_kernel(
    const float* __restrict__ fw, const float* __restrict__ fb)
{
    extern __shared__ float sm[];
    float* s_w = sm;                 // 128*161
    float* s_in = sm + 128 * 161;    // 32*160
    const int tid = threadIdx.x;
    const int b0 = blockIdx.x * 32;

    for (int i = tid; i < 128 * 160; i += 512) {
        int r = i / 160, c = i % 160;
        s_w[r * 161 + c] = fw[i];
    }
    for (int i = tid; i < 32 * 160; i += 512) {
        int s = i / 160, c = i % 160;
        s_in[i] = (c < 128) ? g_ht[(b0 + s) * HH + c] : g_pool[(b0 + s) * 32 + (c - 128)];
    }
    __syncthreads();

    const int g = tid >> 7, j = tid & 127;
    float acc[8];
    float bias = __ldg(fb + j);
#pragma unroll
    for (int ss = 0; ss < 8; ss++) acc[ss] = bias;
    for (int k = 0; k < 160; k++) {
        float w = s_w[j * 161 + k];
#pragma unroll
        for (int ss = 0; ss < 8; ss++)
            acc[ss] = fmaf(w, s_in[(g * 8 + ss) * 160 + k], acc[ss]);
    }
#pragma unroll
    for (int ss = 0; ss < 8; ss++)
        g_fused[(b0 + g * 8 + ss) * HH + j] = fast_tanh(acc[ss]);
}

// ---------------- decoder (R6): 4 rows/thread, NB=8 ----------------------------
__global__ __launch_bounds__(128, 4) void dec_kernel(
    const float* __restrict__ w_ih,
    const float* __restrict__ b_ih, const float* __restrict__ b_hh,
    const float* __restrict__ out_w, const float* __restrict__ out_b,
    float* __restrict__ out)
{
    extern __shared__ float sm[];
    float* s_h   = sm;                 // 2*128*HP = 3072
    float* s_inp = s_h + 2 * HH * HP;  // 16
    float* s_ow  = s_inp + 16;         // 256

    const int j = threadIdx.x;
    const int b0 = blockIdx.x * NB;

    for (int i = j; i < NB * HH; i += 128) {
        int s = i >> 7, k = i & 127;
        s_h[k * HP + s] = g_fused[(long)b0 * HH + i];
    }
    if (j < 16) s_inp[j] = 0.f;
    for (int i = j; i < 256; i += 128) s_ow[i] = out_w[i];
    __syncthreads();

    float bbv[4], wiA[4], wiB[4];
#pragma unroll
    for (int r = 0; r < 4; r++) {
        int row = r * HH + j;
        bbv[r] = __ldg(b_ih + row) + __ldg(b_hh + row);
        wiA[r] = __ldg(w_ih + row * 2);
        wiB[r] = __ldg(w_ih + row * 2 + 1);
    }
    const float ob = out_b[j & 1];
    u64 c2[SP];
#pragma unroll
    for (int sp = 0; sp < SP; sp++) c2[sp] = 0ull;

    const float4* wt4 = (const float4*)g_wtd;
    int cur = 0;
    u64 hu[SP];

    for (int t = 0; t < PRED; t++) {
        const float* hc = s_h + cur * HH * HP;
        float* hn = s_h + (cur ^ 1) * HH * HP;

        u64 acc[4][SP];
#pragma unroll
        for (int sp = 0; sp < SP; sp++) {
            float a0 = s_inp[4 * sp + 0], a1 = s_inp[4 * sp + 1];
            float b0v = s_inp[4 * sp + 2], b1v = s_inp[4 * sp + 3];
#pragma unroll
            for (int r = 0; r < 4; r++) {
                float A = fmaf(wiB[r], a1, fmaf(wiA[r], a0, bbv[r]));
                float B = fmaf(wiB[r], b1v, fmaf(wiA[r], b0v, bbv[r]));
                acc[r][sp] = pk(A, B);
            }
        }

        const ulonglong2* h2 = (const ulonglong2*)hc;
#define KSTEP(CMP, KOFF) { \
            const ulonglong2* hb = h2 + ((kk << 2) + (KOFF)) * (HP / 4); \
            ulonglong2 hA = hb[0], hB = hb[1]; \
            u64 hp[SP] = {hA.x, hA.y, hB.x, hB.y}; \
            u64 W0 = pk(qa.CMP, qa.CMP), W1 = pk(qb.CMP, qb.CMP); \
            u64 W2 = pk(qc.CMP, qc.CMP), W3 = pk(qd.CMP, qd.CMP); \
            _Pragma("unroll") \
            for (int sp = 0; sp < SP; sp++) { \
                fma2(acc[0][sp], W0, hp[sp]); \
                fma2(acc[1][sp], W1, hp[sp]); \
                fma2(acc[2][sp], W2, hp[sp]); \
                fma2(acc[3][sp], W3, hp[sp]); \
            } }

        for (int kk = 0; kk < NK; kk++) {
            float4 qa = wt4[(kk << 9) + j];
            float4 qb = wt4[(kk << 9) + j + 128];
            float4 qc = wt4[(kk << 9) + j + 256];
            float4 qd = wt4[(kk << 9) + j + 384];
            KSTEP(x, 0) KSTEP(y, 1) KSTEP(z, 2) KSTEP(w, 3)
        }
#undef KSTEP

#pragma unroll
        for (int sp = 0; sp < SP; sp++) {
            float2 xi = up2(acc[0][sp]);
            float2 xf = up2(acc[1][sp]);
            float2 xg = up2(acc[2][sp]);
            float2 xo = up2(acc[3][sp]);
            float i0 = fast_sig(xi.x), i1 = fast_sig(xi.y);
            float f0 = fast_sig(xf.x), f1 = fast_sig(xf.y);
            float g0 = fast_tanh(xg.x), g1 = fast_tanh(xg.y);
            float o0 = fast_sig(xo.x), o1 = fast_sig(xo.y);
            float2 cc = up2(c2[sp]);
            float cn0 = fmaf(f0, cc.x, i0 * g0);
            float cn1 = fmaf(f1, cc.y, i1 * g1);
            c2[sp] = pk(cn0, cn1);
            hu[sp] = pk(o0 * fast_tanh(cn0), o1 * fast_tanh(cn1));
        }
        ulonglong2* hw = (ulonglong2*)(hn + j * HP);
        hw[0] = make_ulonglong2(hu[0], hu[1]);
        hw[1] = make_ulonglong2(hu[2], hu[3]);
        __syncthreads();
        cur ^= 1;

        if (j < 16) {
            int s = j >> 1, d = j & 1;
            const float* hw2 = s_ow + d * HH;
            const float* hh = s_h + cur * HH * HP;
            float psum = ob;
#pragma unroll 8
            for (int k = 0; k < HH; k++) psum = fmaf(hw2[k], hh[k * HP + s], psum);
            out[(long)(b0 + s) * (PRED * 2) + t * 2 + d] = psum;
            s_inp[s * 2 + d] = psum;
        }
        __syncthreads();
    }
}

// ---------------- launch ---------------------------------------------------------
extern "C" void kernel_launch(void* const* d_in, const int* in_sizes, int n_in,
                              void* d_out, int out_size)
{
    const float* target  = (const float*)d_in[0];
    const float* neigh   = (const float*)d_in[1];
    const float* enc_w_ih = (const float*)d_in[4];
    const float* enc_w_hh = (const float*)d_in[5];
    const float* enc_b_ih = (const float*)d_in[6];
    const float* enc_b_hh = (const float*)d_in[7];
    const float* nb_w_ih  = (const float*)d_in[8];
    const float* nb_w_hh  = (const float*)d_in[9];
    const float* nb_b_ih  = (const float*)d_in[10];
    const float* nb_b_hh  = (const float*)d_in[11];
    const float* conv1_w  = (const float*)d_in[12];
    const float* conv1_b  = (const float*)d_in[13];
    const float* conv2_w  = (const float*)d_in[14];
    const float* conv2_b  = (const float*)d_in[15];
    const float* fus_w    = (const float*)d_in[16];
    const float* fus_b    = (const float*)d_in[17];
    const float* dec_w_ih = (const float*)d_in[18];
    const float* dec_w_hh = (const float*)d_in[19];
    const float* dec_b_ih = (const float*)d_in[20];
    const float* dec_b_hh = (const float*)d_in[21];
    const float* out_w    = (const float*)d_in[22];
    const float* out_b    = (const float*)d_in[23];
    float* out = (float*)d_out;

    const int ENC_SMEM  = (ENB * TT * FF + 2 * HH * EHP + 4 * HH * FF + 512) * 4;
    const int C1_SMEM   = (8 * 9 * 132 + 32 * 9 * 132) * 4;
    const int C2_SMEM   = (8192 + 32 * 577) * 4;
    const int FUSE_SMEM = (128 * 161 + 32 * 160) * 4;
    const int DEC_SMEM  = (2 * HH * HP + 16 + 256) * 4;

    cudaFuncSetAttribute(enc_kernel,  cudaFuncAttributeMaxDynamicSharedMemorySize, ENC_SMEM);
    cudaFuncSetAttribute(conv1_kernel, cudaFuncAttributeMaxDynamicSharedMemorySize, C1_SMEM);
    cudaFuncSetAttribute(conv2_kernel, cudaFuncAttributeMaxDynamicSharedMemorySize, C2_SMEM);
    cudaFuncSetAttribute(fuse_kernel, cudaFuncAttributeMaxDynamicSharedMemorySize, FUSE_SMEM);
    cudaFuncSetAttribute(dec_kernel,  cudaFuncAttributeMaxDynamicSharedMemorySize, DEC_SMEM);

    float* d_wte; cudaGetSymbolAddress((void**)&d_wte, g_wte);
    float* d_wtn; cudaGetSymbolAddress((void**)&d_wtn, g_wtn);
    float* d_wtd; cudaGetSymbolAddress((void**)&d_wtd, g_wtd);

    transpose_kernel<<<256, 256>>>(enc_w_hh, d_wte);
    transpose_kernel<<<256, 256>>>(nb_w_hh,  d_wtn);
    transpose_kernel<<<256, 256>>>(dec_w_hh, d_wtd);

    // merged encoders: 512 target blocks + 4096 neighbor blocks, 256 threads each
    enc_kernel<<<ETBLK + BATCH * KN / ENB, 256, ENC_SMEM>>>(
        target, neigh, enc_w_ih, nb_w_ih,
        enc_b_ih, enc_b_hh, nb_b_ih, nb_b_hh);

    conv1_kernel<<<BATCH / 8, 256, C1_SMEM>>>(conv1_w, conv1_b);
    conv2_kernel<<<BATCH / 2, 256, C2_SMEM>>>(conv2_w, conv2_b);
    fuse_kernel<<<BATCH / 32, 512, FUSE_SMEM>>>(fus_w, fus_b);
    dec_kernel<<<BATCH / NB, 128, DEC_SMEM>>>(dec_w_ih, dec_b_ih, dec_b_hh,
                                              out_w, out_b, out);
}

// round 14
// speedup vs baseline: 1.0786x; 1.0786x over previous
#include <cuda_runtime.h>
#include <math.h>

#define BATCH 8192
#define KN 8
#define TT 20
#define FF 7
#define HH 128
#define NB 8           // sequences per LSTM block
#define SP (NB/2)      // seq pairs per thread
#define PRED 25
#define TBLK (BATCH/NB)   // 1024 target-encoder blocks
#define HP 12          // padded [k][s] row stride (floats)
#define NK 32

typedef unsigned long long u64;

// ---------------- f32x2 helpers ----------------------------------------------
__device__ __forceinline__ void fma2(u64 &a, u64 x, u64 y){
    asm("fma.rn.f32x2 %0, %1, %2, %0;" : "+l"(a) : "l"(x), "l"(y));
}
__device__ __forceinline__ u64 pk(float lo, float hi){
    u64 r; asm("mov.b64 %0, {%1,%2};" : "=l"(r) : "f"(lo), "f"(hi)); return r;
}
__device__ __forceinline__ float2 up2(u64 a){
    float lo, hi; asm("mov.b64 {%0,%1}, %2;" : "=f"(lo), "=f"(hi) : "l"(a));
    return make_float2(lo, hi);
}
__device__ __forceinline__ float fast_sig(float v){
    return __fdividef(1.f, 1.f + __expf(-v));
}
__device__ __forceinline__ float fast_tanh(float v){
    return 1.f - __fdividef(2.f, 1.f + __expf(2.f * v));
}

// ---------------- scratch ------------------------------------------------------
__device__ float g_ht[BATCH * HH];
__device__ float g_hn[BATCH * KN * HH];
__device__ float g_y1[BATCH * 64 * 64];
__device__ float g_pool[BATCH * 32];
__device__ float g_fused[BATCH * HH];
__device__ float g_wte[NK * 512 * 4];   // w_hh transposed [kk][row][4]
__device__ float g_wtn[NK * 512 * 4];
__device__ float g_wtd[NK * 512 * 4];

// ---------------- w_hh transpose: [row][k] -> [kk][row][4] --------------------
__global__ void transpose_kernel(const float* __restrict__ w, float* __restrict__ wt){
    int i = blockIdx.x * 256 + threadIdx.x;
    int row = i >> 7, k = i & 127;
    int kk = k >> 2, r = k & 3;
    wt[(((kk << 9) + row) << 2) + r] = w[i];
}

// ---------------- merged encoder (R6): 4 rows/thread, NB=8, 4 blocks/SM --------
__global__ __launch_bounds__(128, 4) void enc_kernel(
    const float* __restrict__ tgt_x, const float* __restrict__ nb_x,
    const float* __restrict__ e_wih, const float* __restrict__ n_wih,
    const float* __restrict__ e_bi,  const float* __restrict__ e_bh,
    const float* __restrict__ n_bi,  const float* __restrict__ n_bh)
{
    extern __shared__ float sm[];
    float* s_x   = sm;                       // NB*TT*FF = 1120
    float* s_h   = s_x + NB * TT * FF;       // 2 * 128 * HP = 3072
    float* s_wih = s_h + 2 * HH * HP;        // 3584
    float* s_b   = s_wih + 4 * HH * FF;      // 512

    const int j = threadIdx.x;               // hidden unit 0..127

    const bool is_tgt = (blockIdx.x < TBLK);
    const int seq0 = (is_tgt ? blockIdx.x : (blockIdx.x - TBLK)) * NB;
    const float* x    = is_tgt ? tgt_x : nb_x;
    const float* wih  = is_tgt ? e_wih : n_wih;
    const float* bi   = is_tgt ? e_bi  : n_bi;
    const float* bh   = is_tgt ? e_bh  : n_bh;
    const float* wt   = is_tgt ? g_wte : g_wtn;
    float* h_out      = is_tgt ? g_ht  : g_hn;

    for (int i = j; i < 4 * HH * FF; i += 128) s_wih[i] = wih[i];
    for (int i = j; i < 512; i += 128) s_b[i] = bi[i] + bh[i];
    for (int i = j; i < NB * TT * FF; i += 128) s_x[i] = x[(long)seq0 * (TT * FF) + i];
    for (int i = j; i < HH * HP; i += 128) s_h[i] = 0.f;
    __syncthreads();

    float bbv[4], wi[4][FF];
#pragma unroll
    for (int r = 0; r < 4; r++) {
        bbv[r] = s_b[r * HH + j];
#pragma unroll
        for (int f = 0; f < FF; f++) wi[r][f] = s_wih[(r * HH + j) * FF + f];
    }
    u64 c2[SP];
#pragma unroll
    for (int sp = 0; sp < SP; sp++) c2[sp] = 0ull;

    const float4* wt4 = (const float4*)wt;
    int cur = 0;
    u64 hu[SP];

    for (int t = 0; t < TT; t++) {
        const float* hc = s_h + cur * HH * HP;
        float* hn = s_h + (cur ^ 1) * HH * HP;

        u64 acc[4][SP];
#pragma unroll
        for (int sp = 0; sp < SP; sp++) {
            const float* xa = s_x + ((2 * sp) * TT + t) * FF;
            const float* xb = xa + TT * FF;
            float A[4], B[4];
#pragma unroll
            for (int r = 0; r < 4; r++) { A[r] = bbv[r]; B[r] = bbv[r]; }
#pragma unroll
            for (int f = 0; f < FF; f++) {
                float va = xa[f], vb = xb[f];
#pragma unroll
                for (int r = 0; r < 4; r++) {
                    A[r] = fmaf(wi[r][f], va, A[r]);
                    B[r] = fmaf(wi[r][f], vb, B[r]);
                }
            }
#pragma unroll
            for (int r = 0; r < 4; r++) acc[r][sp] = pk(A[r], B[r]);
        }

        const ulonglong2* h2 = (const ulonglong2*)hc;   // HP/4=3 u2 per k-row
#define KSTEP(CMP, KOFF) { \
            const ulonglong2* hb = h2 + ((kk << 2) + (KOFF)) * (HP / 4); \
            ulonglong2 hA = hb[0], hB = hb[1]; \
            u64 hp[SP] = {hA.x, hA.y, hB.x, hB.y}; \
            u64 W0 = pk(qa.CMP, qa.CMP), W1 = pk(qb.CMP, qb.CMP); \
            u64 W2 = pk(qc.CMP, qc.CMP), W3 = pk(qd.CMP, qd.CMP); \
            _Pragma("unroll") \
            for (int sp = 0; sp < SP; sp++) { \
                fma2(acc[0][sp], W0, hp[sp]); \
                fma2(acc[1][sp], W1, hp[sp]); \
                fma2(acc[2][sp], W2, hp[sp]); \
                fma2(acc[3][sp], W3, hp[sp]); \
            } }

        for (int kk = 0; kk < NK; kk++) {
            float4 qa = wt4[(kk << 9) + j];
            float4 qb = wt4[(kk << 9) + j + 128];
            float4 qc = wt4[(kk << 9) + j + 256];
            float4 qd = wt4[(kk << 9) + j + 384];
            KSTEP(x, 0) KSTEP(y, 1) KSTEP(z, 2) KSTEP(w, 3)
        }
#undef KSTEP

#pragma unroll
        for (int sp = 0; sp < SP; sp++) {
            float2 xi = up2(acc[0][sp]);
            float2 xf = up2(acc[1][sp]);
            float2 xg = up2(acc[2][sp]);
            float2 xo = up2(acc[3][sp]);
            float i0 = fast_sig(xi.x), i1 = fast_sig(xi.y);
            float f0 = fast_sig(xf.x), f1 = fast_sig(xf.y);
            float g0 = fast_tanh(xg.x), g1 = fast_tanh(xg.y);
            float o0 = fast_sig(xo.x), o1 = fast_sig(xo.y);
            float2 cc = up2(c2[sp]);
            float cn0 = fmaf(f0, cc.x, i0 * g0);
            float cn1 = fmaf(f1, cc.y, i1 * g1);
            c2[sp] = pk(cn0, cn1);
            hu[sp] = pk(o0 * fast_tanh(cn0), o1 * fast_tanh(cn1));
        }
        ulonglong2* hw = (ulonglong2*)(hn + j * HP);
        hw[0] = make_ulonglong2(hu[0], hu[1]);
        hw[1] = make_ulonglong2(hu[2], hu[3]);
        __syncthreads();
        cur ^= 1;
    }

    const float* hf = s_h + cur * HH * HP;
    for (int i = j; i < NB * HH; i += 128) {
        int s = i >> 7, k = i & 127;
        h_out[(long)(seq0 + s) * HH + k] = hf[k * HP + s];
    }
}

// ---------------- conv1: sparse social grid, weights staged in smem -----------
__global__ __launch_bounds__(256) void conv1_kernel(
    const float* __restrict__ w1, const float* __restrict__ b1)
{
    extern __shared__ float sm[];
    float* s_v = sm;                 // 8*9*132
    float* s_w = sm + 8 * 9 * 132;   // 32*9*132
    const int tid = threadIdx.x;
    const int b0 = blockIdx.x * 8;

    for (int i = tid; i < 8 * 9 * 128; i += 256) {
        int b = i / 1152, r = i % 1152, cell = r >> 7, c = r & 127;
        float v = (cell == 0) ? g_ht[(b0 + b) * HH + c]
                              : g_hn[((b0 + b) * KN + cell - 1) * HH + c];
        s_v[(b * 9 + cell) * 132 + c] = v;
    }

    const int o = tid >> 3, b = tid & 7;
    const float* vb = s_v + b * 1188;

    for (int half = 0; half < 2; half++) {
        __syncthreads();
        for (int i = tid; i < 32 * 1152; i += 256) {
            int oo = i / 1152, r = i % 1152, c = r / 9, tap = r % 9;
            s_w[oo * 1188 + tap * 132 + c] = w1[half * 32 * 1152 + i];
        }
        __syncthreads();

        const int och = half * 32 + o;
        const float bias = __ldg(b1 + och);
        const float* wb = s_w + o * 1188;
        const int CY[9] = {4, 0, 0, 0, 0, 0, 0, 0, 1};
        const int CX[9] = {4, 1, 2, 3, 4, 5, 6, 7, 0};

        for (int p = 0; p < 8; p++) {
            u64 acc[8];
#pragma unroll
            for (int q = 0; q < 8; q++) acc[q] = pk(bias, 0.f);
#pragma unroll
            for (int ci = 0; ci < 9; ci++) {
                const int cx = CX[ci];
                int dy = CY[ci] - p;
                if (dy < -1 || dy > 1) continue;
                const ulonglong2* vp  = (const ulonglong2*)(vb + ci * 132);
                const ulonglong2* wL  = (const ulonglong2*)(wb + ((dy + 1) * 3 + 2) * 132);
                const ulonglong2* wC  = (const ulonglong2*)(wb + ((dy + 1) * 3 + 1) * 132);
                const ulonglong2* wR  = (const ulonglong2*)(wb + ((dy + 1) * 3 + 0) * 132);
#pragma unroll 8
                for (int cc = 0; cc < 32; cc++) {
                    ulonglong2 vv = vp[cc];
                    if (cx - 1 >= 0) {
                        ulonglong2 wv = wL[cc];
                        fma2(acc[cx - 1], wv.x, vv.x);
                        fma2(acc[cx - 1], wv.y, vv.y);
                    }
                    {
                        ulonglong2 wv = wC[cc];
                        fma2(acc[cx], wv.x, vv.x);
                        fma2(acc[cx], wv.y, vv.y);
                    }
                    if (cx + 1 <= 7) {
                        ulonglong2 wv = wR[cc];
                        fma2(acc[cx + 1], wv.x, vv.x);
                        fma2(acc[cx + 1], wv.y, vv.y);
                    }
                }
            }
            float oq[8];
#pragma unroll
            for (int q = 0; q < 8; q++) {
                float2 f2 = up2(acc[q]);
                oq[q] = fmaxf(f2.x + f2.y, 0.f);
            }
            float4* dst = (float4*)(g_y1 + ((long)(b0 + b) * 64 + och) * 64 + p * 8);
            dst[0] = make_float4(oq[0], oq[1], oq[2], oq[3]);
            dst[1] = make_float4(oq[4], oq[5], oq[6], oq[7]);
        }
    }
}

// ---------------- conv2 + relu + maxpool ---------------------------------------
__global__ __launch_bounds__(256) void conv2_kernel(
    const float* __restrict__ w2, const float* __restrict__ b2)
{
    extern __shared__ float sm[];
    float* s_y = sm;                 // 8192
    float* s_w = sm + 8192;          // 32*577
    const int tid = threadIdx.x;
    const int b0 = blockIdx.x * 2;

    for (int i = tid; i < 8192; i += 256) s_y[i] = g_y1[(long)b0 * 4096 + i];
    for (int i = tid; i < 32 * 576; i += 256) {
        int c2 = i / 576, r = i % 576;
        s_w[c2 * 577 + r] = w2[i];
    }
    __syncthreads();

    const int b  = tid >> 7;
    const int cp = (tid >> 3) & 15;
    const int p  = tid & 7;
    const int c2a = cp, c2b = cp + 16;

    u64 acca[4], accb[4];
#pragma unroll
    for (int m = 0; m < 4; m++) { acca[m] = 0ull; accb[m] = 0ull; }

    for (int ty = 0; ty < 3; ty++) {
        int ip = p + ty - 1;
        if (ip < 0 || ip > 7) continue;
        for (int c1 = 0; c1 < 64; c1++) {
            const float4* yr = (const float4*)(s_y + ((b * 64 + c1) * 64 + ip * 8));
            float4 a0 = yr[0], a1 = yr[1];
            u64 C0 = pk(a0.x, a0.y), C1 = pk(a0.z, a0.w);
            u64 C2 = pk(a1.x, a1.y), C3 = pk(a1.z, a1.w);
            u64 L0 = pk(0.f,  a0.x), L1 = pk(a0.y, a0.z);
            u64 L2 = pk(a0.w, a1.x), L3 = pk(a1.y, a1.z);
            u64 R3 = pk(a1.w, 0.f);
            const float* wpa = s_w + c2a * 577 + c1 * 9 + ty * 3;
            const float* wpb = s_w + c2b * 577 + c1 * 9 + ty * 3;
            u64 W0a = pk(wpa[0], wpa[0]), W1a = pk(wpa[1], wpa[1]), W2a = pk(wpa[2], wpa[2]);
            u64 W0b = pk(wpb[0], wpb[0]), W1b = pk(wpb[1], wpb[1]), W2b = pk(wpb[2], wpb[2]);
            fma2(acca[0], W1a, C0); fma2(acca[1], W1a, C1);
            fma2(acca[2], W1a, C2); fma2(acca[3], W1a, C3);
            fma2(acca[0], W0a, L0); fma2(acca[1], W0a, L1);
            fma2(acca[2], W0a, L2); fma2(acca[3], W0a, L3);
            fma2(acca[0], W2a, L1); fma2(acca[1], W2a, L2);
            fma2(acca[2], W2a, L3); fma2(acca[3], W2a, R3);
            fma2(accb[0], W1b, C0); fma2(accb[1], W1b, C1);
            fma2(accb[2], W1b, C2); fma2(accb[3], W1b, C3);
            fma2(accb[0], W0b, L0); fma2(accb[1], W0b, L1);
            fma2(accb[2], W0b, L2); fma2(accb[3], W0b, L3);
            fma2(accb[0], W2b, L1); fma2(accb[1], W2b, L2);
            fma2(accb[2], W2b, L3); fma2(accb[3], W2b, R3);
        }
    }
    float bia = __ldg(b2 + c2a), bib = __ldg(b2 + c2b);
    float ma = 0.f, mb = 0.f;
#pragma unroll
    for (int m = 0; m < 4; m++) {
        float2 fa = up2(acca[m]);
        float2 fb = up2(accb[m]);
        ma = fmaxf(ma, fmaxf(fa.x, fa.y) + bia);
        mb = fmaxf(mb, fmaxf(fb.x, fb.y) + bib);
    }
    for (int off = 4; off; off >>= 1) {
        ma = fmaxf(ma, __shfl_xor_sync(0xffffffffu, ma, off));
        mb = fmaxf(mb, __shfl_xor_sync(0xffffffffu, mb, off));
    }
    if (p == 0) {
        g_pool[(b0 + b) * 32 + c2a] = ma;
        g_pool[(b0 + b) * 32 + c2b] = mb;
    }
}

// ---------------- fusion --------------------------------------------------------
__global__ __launch_bounds__(512) void fuse_kernel(
    const float* __restrict__ fw, const float* __restrict__ fb)
{
    extern __shared__ float sm[];
    float* s_w = sm;                 // 128*161
    float* s_in = sm + 128 * 161;    // 32*160
    const int tid = threadIdx.x;
    const int b0 = blockIdx.x * 32;

    for (int i = tid; i < 128 * 160; i += 512) {
        int r = i / 160, c = i % 160;
        s_w[r * 161 + c] = fw[i];
    }
    for (int i = tid; i < 32 * 160; i += 512) {
        int s = i / 160, c = i % 160;
        s_in[i] = (c < 128) ? g_ht[(b0 + s) * HH + c] : g_pool[(b0 + s) * 32 + (c - 128)];
    }
    __syncthreads();

    const int g = tid >> 7, j = tid & 127;
    float acc[8];
    float bias = __ldg(fb + j);
#pragma unroll
    for (int ss = 0; ss < 8; ss++) acc[ss] = bias;
    for (int k = 0; k < 160; k++) {
        float w = s_w[j * 161 + k];
#pragma unroll
        for (int ss = 0; ss < 8; ss++)
            acc[ss] = fmaf(w, s_in[(g * 8 + ss) * 160 + k], acc[ss]);
    }
#pragma unroll
    for (int ss = 0; ss < 8; ss++)
        g_fused[(b0 + g * 8 + ss) * HH + j] = fast_tanh(acc[ss]);
}

// ---------------- decoder (R6 body + parallel out-projection) ------------------
__global__ __launch_bounds__(128, 4) void dec_kernel(
    const float* __restrict__ w_ih,
    const float* __restrict__ b_ih, const float* __restrict__ b_hh,
    const float* __restrict__ out_w, const float* __restrict__ out_b,
    float* __restrict__ out)
{
    extern __shared__ float sm[];
    float* s_h   = sm;                 // 2*128*HP = 3072
    float* s_inp = s_h + 2 * HH * HP;  // 16
    float* s_ow  = s_inp + 16;         // 256

    const int j = threadIdx.x;
    const int b0 = blockIdx.x * NB;

    for (int i = j; i < NB * HH; i += 128) {
        int s = i >> 7, k = i & 127;
        s_h[k * HP + s] = g_fused[(long)b0 * HH + i];
    }
    if (j < 16) s_inp[j] = 0.f;
    for (int i = j; i < 256; i += 128) s_ow[i] = out_w[i];
    __syncthreads();

    float bbv[4], wiA[4], wiB[4];
#pragma unroll
    for (int r = 0; r < 4; r++) {
        int row = r * HH + j;
        bbv[r] = __ldg(b_ih + row) + __ldg(b_hh + row);
        wiA[r] = __ldg(w_ih + row * 2);
        wiB[r] = __ldg(w_ih + row * 2 + 1);
    }

    // parallel out-projection mapping: 8 threads per output value (16 outputs)
    const int oo = j >> 3;
    const int p8 = j & 7;
    const int os = oo >> 1, od = oo & 1;
    const float obv = __ldg(out_b + od);

    u64 c2[SP];
#pragma unroll
    for (int sp = 0; sp < SP; sp++) c2[sp] = 0ull;

    const float4* wt4 = (const float4*)g_wtd;
    int cur = 0;
    u64 hu[SP];

    for (int t = 0; t < PRED; t++) {
        const float* hc = s_h + cur * HH * HP;
        float* hn = s_h + (cur ^ 1) * HH * HP;

        u64 acc[4][SP];
#pragma unroll
        for (int sp = 0; sp < SP; sp++) {
            float a0 = s_inp[4 * sp + 0], a1 = s_inp[4 * sp + 1];
            float b0v = s_inp[4 * sp + 2], b1v = s_inp[4 * sp + 3];
#pragma unroll
            for (int r = 0; r < 4; r++) {
                float A = fmaf(wiB[r], a1, fmaf(wiA[r], a0, bbv[r]));
                float B = fmaf(wiB[r], b1v, fmaf(wiA[r], b0v, bbv[r]));
                acc[r][sp] = pk(A, B);
            }
        }

        const ulonglong2* h2 = (const ulonglong2*)hc;
#define KSTEP(CMP, KOFF) { \
            const ulonglong2* hb = h2 + ((kk << 2) + (KOFF)) * (HP / 4); \
            ulonglong2 hA = hb[0], hB = hb[1]; \
            u64 hp[SP] = {hA.x, hA.y, hB.x, hB.y}; \
            u64 W0 = pk(qa.CMP, qa.CMP), W1 = pk(qb.CMP, qb.CMP); \
            u64 W2 = pk(qc.CMP, qc.CMP), W3 = pk(qd.CMP, qd.CMP); \
            _Pragma("unroll") \
            for (int sp = 0; sp < SP; sp++) { \
                fma2(acc[0][sp], W0, hp[sp]); \
                fma2(acc[1][sp], W1, hp[sp]); \
                fma2(acc[2][sp], W2, hp[sp]); \
                fma2(acc[3][sp], W3, hp[sp]); \
            } }

        for (int kk = 0; kk < NK; kk++) {
            float4 qa = wt4[(kk << 9) + j];
            float4 qb = wt4[(kk << 9) + j + 128];
            float4 qc = wt4[(kk << 9) + j + 256];
            float4 qd = wt4[(kk << 9) + j + 384];
            KSTEP(x, 0) KSTEP(y, 1) KSTEP(z, 2) KSTEP(w, 3)
        }
#undef KSTEP

#pragma unroll
        for (int sp = 0; sp < SP; sp++) {
            float2 xi = up2(acc[0][sp]);
            float2 xf = up2(acc[1][sp]);
            float2 xg = up2(acc[2][sp]);
            float2 xo = up2(acc[3][sp]);
            float i0 = fast_sig(xi.x), i1 = fast_sig(xi.y);
            float f0 = fast_sig(xf.x), f1 = fast_sig(xf.y);
            float g0 = fast_tanh(xg.x), g1 = fast_tanh(xg.y);
            float o0 = fast_sig(xo.x), o1 = fast_sig(xo.y);
            float2 cc = up2(c2[sp]);
            float cn0 = fmaf(f0, cc.x, i0 * g0);
            float cn1 = fmaf(f1, cc.y, i1 * g1);
            c2[sp] = pk(cn0, cn1);
            hu[sp] = pk(o0 * fast_tanh(cn0), o1 * fast_tanh(cn1));
        }
        ulonglong2* hw = (ulonglong2*)(hn + j * HP);
        hw[0] = make_ulonglong2(hu[0], hu[1]);
        hw[1] = make_ulonglong2(hu[2], hu[3]);
        __syncthreads();
        cur ^= 1;

        // parallel output projection: 8 threads x 16 strided partials per output
        {
            const float* hw2 = s_ow + od * HH;
            const float* hh = s_h + cur * HH * HP;
            float psum = 0.f;
#pragma unroll
            for (int kq = 0; kq < 16; kq++) {
                int k = p8 + (kq << 3);
                psum = fmaf(hw2[k], hh[k * HP + os], psum);
            }
            psum += __shfl_xor_sync(0xffffffffu, psum, 1);
            psum += __shfl_xor_sync(0xffffffffu, psum, 2);
            psum += __shfl_xor_sync(0xffffffffu, psum, 4);
            if (p8 == 0) {
                float v = psum + obv;
                out[(long)(b0 + os) * (PRED * 2) + t * 2 + od] = v;
                s_inp[os * 2 + od] = v;
            }
        }
        __syncthreads();
    }
}

// ---------------- launch ---------------------------------------------------------
extern "C" void kernel_launch(void* const* d_in, const int* in_sizes, int n_in,
                              void* d_out, int out_size)
{
    const float* target  = (const float*)d_in[0];
    const float* neigh   = (const float*)d_in[1];
    const float* enc_w_ih = (const float*)d_in[4];
    const float* enc_w_hh = (const float*)d_in[5];
    const float* enc_b_ih = (const float*)d_in[6];
    const float* enc_b_hh = (const float*)d_in[7];
    const float* nb_w_ih  = (const float*)d_in[8];
    const float* nb_w_hh  = (const float*)d_in[9];
    const float* nb_b_ih  = (const float*)d_in[10];
    const float* nb_b_hh  = (const float*)d_in[11];
    const float* conv1_w  = (const float*)d_in[12];
    const float* conv1_b  = (const float*)d_in[13];
    const float* conv2_w  = (const float*)d_in[14];
    const float* conv2_b  = (const float*)d_in[15];
    const float* fus_w    = (const float*)d_in[16];
    const float* fus_b    = (const float*)d_in[17];
    const float* dec_w_ih = (const float*)d_in[18];
    const float* dec_w_hh = (const float*)d_in[19];
    const float* dec_b_ih = (const float*)d_in[20];
    const float* dec_b_hh = (const float*)d_in[21];
    const float* out_w    = (const float*)d_in[22];
    const float* out_b    = (const float*)d_in[23];
    float* out = (float*)d_out;

    const int ENC_SMEM  = (NB * TT * FF + 2 * HH * HP + 4 * HH * FF + 512) * 4;
    const int C1_SMEM   = (8 * 9 * 132 + 32 * 9 * 132) * 4;
    const int C2_SMEM   = (8192 + 32 * 577) * 4;
    const int FUSE_SMEM = (128 * 161 + 32 * 160) * 4;
    const int DEC_SMEM  = (2 * HH * HP + 16 + 256) * 4;

    cudaFuncSetAttribute(enc_kernel,  cudaFuncAttributeMaxDynamicSharedMemorySize, ENC_SMEM);
    cudaFuncSetAttribute(conv1_kernel, cudaFuncAttributeMaxDynamicSharedMemorySize, C1_SMEM);
    cudaFuncSetAttribute(conv2_kernel, cudaFuncAttributeMaxDynamicSharedMemorySize, C2_SMEM);
    cudaFuncSetAttribute(fuse_kernel, cudaFuncAttributeMaxDynamicSharedMemorySize, FUSE_SMEM);
    cudaFuncSetAttribute(dec_kernel,  cudaFuncAttributeMaxDynamicSharedMemorySize, DEC_SMEM);

    float* d_wte; cudaGetSymbolAddress((void**)&d_wte, g_wte);
    float* d_wtn; cudaGetSymbolAddress((void**)&d_wtn, g_wtn);
    float* d_wtd; cudaGetSymbolAddress((void**)&d_wtd, g_wtd);

    transpose_kernel<<<256, 256>>>(enc_w_hh, d_wte);
    transpose_kernel<<<256, 256>>>(nb_w_hh,  d_wtn);
    transpose_kernel<<<256, 256>>>(dec_w_hh, d_wtd);

    // merged encoders: 1024 target blocks + 8192 neighbor blocks
    enc_kernel<<<TBLK + BATCH * KN / NB, 128, ENC_SMEM>>>(
        target, neigh, enc_w_ih, nb_w_ih,
        enc_b_ih, enc_b_hh, nb_b_ih, nb_b_hh);

    conv1_kernel<<<BATCH / 8, 256, C1_SMEM>>>(conv1_w, conv1_b);
    conv2_kernel<<<BATCH / 2, 256, C2_SMEM>>>(conv2_w, conv2_b);
    fuse_kernel<<<BATCH / 32, 512, FUSE_SMEM>>>(fus_w, fus_b);
    dec_kernel<<<BATCH / NB, 128, DEC_SMEM>>>(dec_w_ih, dec_b_ih, dec_b_hh,
                                              out_w, out_b, out);
}